// round 5
// baseline (speedup 1.0000x reference)
#include <cuda_runtime.h>
#include <cstdint>

#define T_DIM   4096
#define B_DIM   8192
#define CL      64
#define CHUNKS  (T_DIM / CL)            // 64
#define THREADS 256
#define SPT     2
#define SEQ_PER_BLK (THREADS * SPT)     // 512
#define BGROUPS (B_DIM / SEQ_PER_BLK)   // 16
#define NBLOCKS (BGROUPS * CHUNKS)      // 1024

// Scratch (allocation-free device globals). ~12 MB, L2-resident.
__device__ float g_agg[3][CHUNKS * B_DIM];   // chunk-local aggregates (n1t, n11, na1)
__device__ float g_pre[3][CHUNKS * B_DIM];   // inclusive prefixes
__device__ int   g_flag[CHUNKS * BGROUPS];   // 0=empty, 1=AGG, 2=PREFIX

__device__ __forceinline__ int ld_acquire(const int* p) {
    int v;
    asm volatile("ld.global.acquire.gpu.b32 %0, [%1];" : "=r"(v) : "l"(p) : "memory");
    return v;
}
__device__ __forceinline__ void st_release(int* p, int v) {
    asm volatile("st.global.release.gpu.b32 [%0], %1;" :: "l"(p), "r"(v) : "memory");
}

__global__ void lk_reset() {
    int i = blockIdx.x * blockDim.x + threadIdx.x;
    if (i < CHUNKS * BGROUPS) g_flag[i] = 0;
}

__global__ void __launch_bounds__(THREADS, 4) lk_main(const float* __restrict__ in,
                                                      const float* __restrict__ dptr,
                                                      float* __restrict__ out) {
    const float d = dptr[0];
    float dL = d;
#pragma unroll
    for (int i = 0; i < 6; ++i) dL *= dL;              // d^CL (CL=64)

    const int bid = blockIdx.x;
    const int c   = bid % CHUNKS;                       // chunk index (fast dim -> predecessors at lower bid)
    const int grp = bid / CHUNKS;
    const int b0  = grp * SEQ_PER_BLK + threadIdx.x * SPT;
    const int lane = threadIdx.x & 31;

    // ---------------- Phase 1: load slab, local scan from zero init ----------------
    float prev_bit[SPT] = {0.f, 0.f};
    if (c != 0) {
        float2 pv = *(const float2*)(in + ((size_t)(c * CL) - 1) * B_DIM + b0);
        prev_bit[0] = pv.x; prev_bit[1] = pv.y;
    }
    float prev_d[SPT] = {prev_bit[0] * d, prev_bit[1] * d};

    float n1t[SPT] = {0.f, 0.f};   // n10 + n11
    float n11[SPT] = {0.f, 0.f};
    float na1[SPT] = {0.f, 0.f};
    uint64_t bits[SPT] = {0ull, 0ull};

    const float2* __restrict__ p = (const float2*)(in + (size_t)(c * CL) * B_DIM + b0);

#pragma unroll
    for (int ii = 0; ii < CL; ii += 8) {
        float2 x[8];
#pragma unroll
        for (int j = 0; j < 8; ++j)
            x[j] = p[(size_t)(ii + j) * (B_DIM / 2)];
#pragma unroll
        for (int j = 0; j < 8; ++j) {
            float xs[SPT] = {x[j].x, x[j].y};
#pragma unroll
            for (int s = 0; s < SPT; ++s) {
                float curf = xs[s];                          // 0.0f or 1.0f
                bits[s] |= (uint64_t)(curf != 0.f) << (ii + j);
                float cur_d = curf * d;
                n11[s] = fmaf(d, n11[s], curf * prev_d[s]);
                na1[s] = fmaf(d, na1[s], prev_d[s]);
                n1t[s] = fmaf(d, n1t[s], cur_d);
                prev_d[s] = cur_d;
            }
        }
    }

    const size_t si = (size_t)c * B_DIM + b0;
    int* flag_self = &g_flag[c * BGROUPS + grp];

    // ---------------- Phase 2: publish + decoupled lookback ----------------
    float ex_t[SPT] = {0.f, 0.f};
    float ex_1[SPT] = {0.f, 0.f};
    float ex_a[SPT] = {0.f, 0.f};

    if (c == 0) {
        // Inclusive prefix == local aggregate; publish PREFIX directly.
        *(float2*)&g_pre[0][si] = make_float2(n1t[0], n1t[1]);
        *(float2*)&g_pre[1][si] = make_float2(n11[0], n11[1]);
        *(float2*)&g_pre[2][si] = make_float2(na1[0], na1[1]);
        __threadfence();
        __syncthreads();
        if (threadIdx.x == 0) st_release(flag_self, 2);
    } else {
        *(float2*)&g_agg[0][si] = make_float2(n1t[0], n1t[1]);
        *(float2*)&g_agg[1][si] = make_float2(n11[0], n11[1]);
        *(float2*)&g_agg[2][si] = make_float2(na1[0], na1[1]);
        __threadfence();
        __syncthreads();
        if (threadIdx.x == 0) st_release(flag_self, 1);

        // Lookback: ex_c = sum_{j<c} dL^{c-1-j} * local_j, short-circuit on PREFIX.
        float f = 1.f;
        int j = c - 1;
        for (;;) {
            int fl = 0;
            if (lane == 0) {
                const int* fp = &g_flag[j * BGROUPS + grp];
                fl = ld_acquire(fp);
                while (fl == 0) { __nanosleep(64); fl = ld_acquire(fp); }
            }
            fl = __shfl_sync(0xffffffffu, fl, 0);

            const size_t sj = (size_t)j * B_DIM + b0;
            const float* a0 = (fl == 2) ? g_pre[0] : g_agg[0];
            const float* a1 = (fl == 2) ? g_pre[1] : g_agg[1];
            const float* a2 = (fl == 2) ? g_pre[2] : g_agg[2];
            float2 vt = *(const float2*)&a0[sj];
            float2 v1 = *(const float2*)&a1[sj];
            float2 va = *(const float2*)&a2[sj];
            ex_t[0] = fmaf(f, vt.x, ex_t[0]); ex_t[1] = fmaf(f, vt.y, ex_t[1]);
            ex_1[0] = fmaf(f, v1.x, ex_1[0]); ex_1[1] = fmaf(f, v1.y, ex_1[1]);
            ex_a[0] = fmaf(f, va.x, ex_a[0]); ex_a[1] = fmaf(f, va.y, ex_a[1]);
            if (fl == 2) break;
            f *= dL;
            if (--j < 0) break;   // safety; chunk 0 always ends at PREFIX
        }

        // Publish own inclusive prefix: inc = local + dL * ex.
        *(float2*)&g_pre[0][si] = make_float2(fmaf(dL, ex_t[0], n1t[0]), fmaf(dL, ex_t[1], n1t[1]));
        *(float2*)&g_pre[1][si] = make_float2(fmaf(dL, ex_1[0], n11[0]), fmaf(dL, ex_1[1], n11[1]));
        *(float2*)&g_pre[2][si] = make_float2(fmaf(dL, ex_a[0], na1[0]), fmaf(dL, ex_a[1], na1[1]));
        __threadfence();
        __syncthreads();
        if (threadIdx.x == 0) st_release(flag_self, 2);
    }

    // ---------------- Phase 3: replay from carry-in, emit predictions ----------------
    // Deterministic all-count carry-in: S = d * (1 - dL^c) / (1 - d).
    float dcs = 1.f, base = dL;
    int e = c;
    while (e) { if (e & 1) dcs *= base; base *= base; e >>= 1; }
    float S = (c == 0) ? 0.f : d * (1.f - dcs) / (1.f - d);

    float r1t[SPT] = {ex_t[0], ex_t[1]};
    float r11[SPT] = {ex_1[0], ex_1[1]};
    float ra1[SPT] = {ex_a[0], ex_a[1]};
    float pd[SPT]  = {prev_bit[0] * d, prev_bit[1] * d};

    float2* __restrict__ po = (float2*)(out + (size_t)(c * CL) * B_DIM + b0);

#pragma unroll 16
    for (int i = 0; i < CL; ++i) {
        S = fmaf(d, S, d);                               // shared across sequences
        float ov[SPT];
#pragma unroll
        for (int s = 0; s < SPT; ++s) {
            bool cur = (bits[s] >> i) & 1ull;
            float cur_d = cur ? d : 0.f;
            r11[s] = fmaf(d, r11[s], cur ? pd[s] : 0.f);
            ra1[s] = fmaf(d, ra1[s], pd[s]);
            r1t[s] = fmaf(d, r1t[s], cur_d);
            pd[s] = cur_d;
            float num = (cur ? r11[s] : r1t[s] - r11[s]) + 1.f;
            float den = (cur ? ra1[s] : S - ra1[s]) + 2.f;
            ov[s] = __fdividef(num, den);
        }
        __stcs(po + (size_t)i * (B_DIM / 2), make_float2(ov[0], ov[1]));
    }
}

// ---------------------------------------------------------------------------
extern "C" void kernel_launch(void* const* d_in, const int* in_sizes, int n_in,
                              void* d_out, int out_size) {
    const float* in   = (const float*)d_in[0];
    const float* dptr = (const float*)d_in[1];
    if (n_in >= 2 && in_sizes[0] == 1) {  // defensive: metadata order swap
        in   = (const float*)d_in[1];
        dptr = (const float*)d_in[0];
    }
    float* out = (float*)d_out;

    lk_reset<<<1, 1024>>>();
    lk_main<<<NBLOCKS, THREADS>>>(in, dptr, out);
}

// round 6
// speedup vs baseline: 1.2681x; 1.2681x over previous
#include <cuda_runtime.h>
#include <cstdint>

#define T_DIM  4096
#define B_DIM  8192
#define CHUNKS 128
#define CL     32          // chunk length; CHUNKS*CL == T_DIM
#define GROUPS (B_DIM / 4) // thread-groups across batch (4 seqs per thread)
#define TPB    128

// Scratch: static device globals (allocation-free). 16 MB total.
__device__ uint32_t g_bits[CHUNKS * B_DIM];          // 4 MB packed inputs
__device__ float    g_state[3][CHUNKS * B_DIM];      // 12 MB chunk states (n1tot, n11, na1)

// ---------------------------------------------------------------------------
// Pass 1: per-chunk local recurrence from zero init; pack input bits.
// 4 seqs/thread (float4), explicit 8-deep load batches for guaranteed MLP.
// ---------------------------------------------------------------------------
__global__ void __launch_bounds__(TPB) lk_pass1(const float* __restrict__ in,
                                                const float* __restrict__ dptr) {
    const float d = dptr[0];
    const int c  = blockIdx.y;
    const int g  = blockIdx.x * TPB + threadIdx.x; // 0..GROUPS-1
    const int b0 = g * 4;

    // prev_d = d * x[c*CL - 1]  (zero for first chunk)
    float prev_d[4] = {0.f, 0.f, 0.f, 0.f};
    if (c != 0) {
        float4 pv = *(const float4*)(in + (size_t)(c * CL - 1) * B_DIM + b0);
        prev_d[0] = pv.x * d; prev_d[1] = pv.y * d;
        prev_d[2] = pv.z * d; prev_d[3] = pv.w * d;
    }

    float n1t[4] = {0.f, 0.f, 0.f, 0.f};   // n10 + n11
    float n11[4] = {0.f, 0.f, 0.f, 0.f};
    float na1[4] = {0.f, 0.f, 0.f, 0.f};
    uint32_t bw[4] = {0u, 0u, 0u, 0u};

    const float4* __restrict__ p = (const float4*)(in + (size_t)(c * CL) * B_DIM + b0);

#pragma unroll
    for (int ii = 0; ii < CL; ii += 8) {
        float4 x[8];
#pragma unroll
        for (int j = 0; j < 8; ++j)
            x[j] = p[(size_t)(ii + j) * (B_DIM / 4)];
#pragma unroll
        for (int j = 0; j < 8; ++j) {
            float xs[4] = {x[j].x, x[j].y, x[j].z, x[j].w};
#pragma unroll
            for (int s = 0; s < 4; ++s) {
                float curf = xs[s];                      // 0.0f or 1.0f
                bw[s] |= (curf != 0.f) ? (1u << (ii + j)) : 0u;
                float cur_d = curf * d;
                n11[s] = fmaf(d, n11[s], curf * prev_d[s]);
                na1[s] = fmaf(d, na1[s], prev_d[s]);
                n1t[s] = fmaf(d, n1t[s], cur_d);
                prev_d[s] = cur_d;
            }
        }
    }

    *(uint4*)(g_bits + (size_t)c * B_DIM + b0) = make_uint4(bw[0], bw[1], bw[2], bw[3]);
    const size_t si = (size_t)c * B_DIM + b0;
    *(float4*)(&g_state[0][si]) = make_float4(n1t[0], n1t[1], n1t[2], n1t[3]);
    *(float4*)(&g_state[1][si]) = make_float4(n11[0], n11[1], n11[2], n11[3]);
    *(float4*)(&g_state[2][si]) = make_float4(na1[0], na1[1], na1[2], na1[3]);
}

// ---------------------------------------------------------------------------
// Pass 2: exclusive scan over chunk states: carry_c = local_c + d^CL * carry_{c-1}.
// Rewrites g_state[comp][c][b] to the INITIAL (carry-in) state for chunk c.
// ---------------------------------------------------------------------------
__global__ void __launch_bounds__(256) lk_pass2(const float* __restrict__ dptr) {
    const float d = dptr[0];
    float dL = d;
#pragma unroll
    for (int i = 0; i < 5; ++i) dL *= dL;  // d^32 by repeated squaring

    const int comp = blockIdx.y;  // 0..2
    const int b    = blockIdx.x * blockDim.x + threadIdx.x;
    float* a = g_state[comp];

    float acc = 0.f;
#pragma unroll
    for (int batch = 0; batch < CHUNKS / 32; ++batch) {
        float v[32];
#pragma unroll
        for (int j = 0; j < 32; ++j)
            v[j] = a[(size_t)(batch * 32 + j) * B_DIM + b];
#pragma unroll
        for (int j = 0; j < 32; ++j) {
            float nv = fmaf(dL, acc, v[j]);
            v[j] = acc;           // exclusive prefix
            acc = nv;
        }
#pragma unroll
        for (int j = 0; j < 32; ++j)
            a[(size_t)(batch * 32 + j) * B_DIM + b] = v[j];
    }
}

// ---------------------------------------------------------------------------
// Pass 3: replay recurrence from corrected init using packed bits; emit preds.
// na0 reconstructed from the deterministic all-count S_t; n10 = n1tot - n11.
// ---------------------------------------------------------------------------
__global__ void __launch_bounds__(TPB) lk_pass3(const float* __restrict__ dptr,
                                                float* __restrict__ out) {
    const float d = dptr[0];
    const int c  = blockIdx.y;
    const int g  = blockIdx.x * TPB + threadIdx.x;
    const int b0 = g * 4;
    const size_t si = (size_t)c * B_DIM + b0;

    float4 v1t = *(const float4*)(&g_state[0][si]);
    float4 v11 = *(const float4*)(&g_state[1][si]);
    float4 va1 = *(const float4*)(&g_state[2][si]);
    float n1t[4] = {v1t.x, v1t.y, v1t.z, v1t.w};
    float n11[4] = {v11.x, v11.y, v11.z, v11.w};
    float na1[4] = {va1.x, va1.y, va1.z, va1.w};

    // Deterministic total-count carry-in: S = d * (1 - d^{c*CL}) / (1 - d)
    float dL = d;
#pragma unroll
    for (int i = 0; i < 5; ++i) dL *= dL;   // d^CL
    float dcs = 1.f, base = dL;
    int e = c;
    while (e) { if (e & 1) dcs *= base; base *= base; e >>= 1; }
    float S = (c == 0) ? 0.f : d * (1.f - dcs) / (1.f - d);

    // prev_d from last bit of previous chunk
    float prev_d[4] = {0.f, 0.f, 0.f, 0.f};
    if (c != 0) {
        uint4 pw = *(const uint4*)(g_bits + (size_t)(c - 1) * B_DIM + b0);
        prev_d[0] = (pw.x >> 31) ? d : 0.f;
        prev_d[1] = (pw.y >> 31) ? d : 0.f;
        prev_d[2] = (pw.z >> 31) ? d : 0.f;
        prev_d[3] = (pw.w >> 31) ? d : 0.f;
    }

    uint4 bwv = *(const uint4*)(g_bits + (size_t)c * B_DIM + b0);
    uint32_t bw[4] = {bwv.x, bwv.y, bwv.z, bwv.w};

    float4* __restrict__ po = (float4*)(out + (size_t)(c * CL) * B_DIM + b0);

#pragma unroll
    for (int i = 0; i < CL; ++i) {
        S = fmaf(d, S, d);  // shared across the 4 sequences
        float ov[4];
#pragma unroll
        for (int s = 0; s < 4; ++s) {
            bool cur = (bw[s] >> i) & 1u;
            float cur_d = cur ? d : 0.f;
            n11[s] = fmaf(d, n11[s], cur ? prev_d[s] : 0.f);
            na1[s] = fmaf(d, na1[s], prev_d[s]);
            n1t[s] = fmaf(d, n1t[s], cur_d);
            prev_d[s] = cur_d;
            float num = (cur ? n11[s] : n1t[s] - n11[s]) + 1.f;
            float den = (cur ? na1[s] : S - na1[s]) + 2.f;
            ov[s] = __fdividef(num, den);
        }
        po[(size_t)i * (B_DIM / 4)] = make_float4(ov[0], ov[1], ov[2], ov[3]);
    }
}

// ---------------------------------------------------------------------------
extern "C" void kernel_launch(void* const* d_in, const int* in_sizes, int n_in,
                              void* d_out, int out_size) {
    const float* in   = (const float*)d_in[0];
    const float* dptr = (const float*)d_in[1];
    if (n_in >= 2 && in_sizes[0] == 1) {  // defensive: metadata order swap
        in   = (const float*)d_in[1];
        dptr = (const float*)d_in[0];
    }
    float* out = (float*)d_out;

    dim3 grid13(GROUPS / TPB, CHUNKS);   // (16, 128) = 2048 blocks
    dim3 grid2(B_DIM / 256, 3);          // (32, 3)

    lk_pass1<<<grid13, TPB>>>(in, dptr);
    lk_pass2<<<grid2, 256>>>(dptr);
    lk_pass3<<<grid13, TPB>>>(dptr, out);
}